// round 2
// baseline (speedup 1.0000x reference)
#include <cuda_runtime.h>
#include <cstdint>

// Problem shape (fixed by reference)
#define BATCH 8
#define NSEQ  2048
#define DDIM  384

// Scratch for PW = P @ W  (8*2048*384 floats = 25.2 MB) — device global, no alloc.
__device__ float g_PW[BATCH * NSEQ * DDIM];

__device__ __forceinline__ unsigned f2tf(float x) {
    unsigned r;
    asm("cvt.rna.tf32.f32 %0, %1;" : "=r"(r) : "f"(x));
    return r;
}

__device__ __forceinline__ void mma_tf32(float& d0, float& d1, float& d2, float& d3,
                                         unsigned a0, unsigned a1, unsigned a2, unsigned a3,
                                         unsigned b0, unsigned b1) {
    asm volatile(
        "mma.sync.aligned.m16n8k8.row.col.f32.tf32.tf32.f32 "
        "{%0,%1,%2,%3}, {%4,%5,%6,%7}, {%8,%9}, {%0,%1,%2,%3};"
        : "+f"(d0), "+f"(d1), "+f"(d2), "+f"(d3)
        : "r"(a0), "r"(a1), "r"(a2), "r"(a3), "r"(b0), "r"(b1));
}

// ============================================================================
// Kernel 1: PW[(b*N)+i][:] = P[(b*N)+i][:] @ W      (one flat [16384,384]x[384,384])
// Tiles: BM=128, BN=128, BK=32. 256 threads, 8 warps (4 row x 2 col),
// warp tile 32x64 -> 2x8 m16n8k8 mmas per k-step.
// ============================================================================
__global__ __launch_bounds__(256, 2)
void gemm_pw_kernel(const float* __restrict__ P, const float* __restrict__ W) {
    __shared__ float As[128][36];   // A tile, K-contig rows; pad 36 -> conflict-free frags
    __shared__ float Ws[32][136];   // W tile [k][n]; pad 136 -> conflict-free frags

    const int t    = threadIdx.x;
    const int lane = t & 31;
    const int warp = t >> 5;
    const int wR   = warp & 3;      // 0..3 row warps
    const int wC   = warp >> 2;     // 0..1 col warps
    const int mBase = blockIdx.y * 128;
    const int nBase = blockIdx.x * 128;

    float acc[2][8][4];
    #pragma unroll
    for (int mt = 0; mt < 2; ++mt)
        #pragma unroll
        for (int nt = 0; nt < 8; ++nt)
            #pragma unroll
            for (int r = 0; r < 4; ++r) acc[mt][nt][r] = 0.f;

    for (int kc = 0; kc < DDIM; kc += 32) {
        // Load A (P rows, 128x32) as float4, convert to tf32 at store.
        #pragma unroll
        for (int p = 0; p < 4; ++p) {
            int id = t + p * 256;            // 0..1023 float4 slots
            int r  = id >> 3;                // 0..127
            int c4 = (id & 7) << 2;          // 0,4,..28
            float4 v = *reinterpret_cast<const float4*>(
                &P[(size_t)(mBase + r) * DDIM + kc + c4]);
            As[r][c4 + 0] = __uint_as_float(f2tf(v.x));
            As[r][c4 + 1] = __uint_as_float(f2tf(v.y));
            As[r][c4 + 2] = __uint_as_float(f2tf(v.z));
            As[r][c4 + 3] = __uint_as_float(f2tf(v.w));
        }
        // Load W tile (32x128)
        #pragma unroll
        for (int p = 0; p < 4; ++p) {
            int id = t + p * 256;
            int r  = id >> 5;                // 0..31 (k)
            int c4 = (id & 31) << 2;         // 0..124 (n)
            float4 v = *reinterpret_cast<const float4*>(
                &W[(size_t)(kc + r) * DDIM + nBase + c4]);
            Ws[r][c4 + 0] = __uint_as_float(f2tf(v.x));
            Ws[r][c4 + 1] = __uint_as_float(f2tf(v.y));
            Ws[r][c4 + 2] = __uint_as_float(f2tf(v.z));
            Ws[r][c4 + 3] = __uint_as_float(f2tf(v.w));
        }
        __syncthreads();

        #pragma unroll
        for (int ks = 0; ks < 4; ++ks) {
            const int k0 = ks * 8;
            unsigned a[2][4], bf[8][2];
            #pragma unroll
            for (int mt = 0; mt < 2; ++mt) {
                int rb = wR * 32 + mt * 16 + (lane >> 2);
                a[mt][0] = __float_as_uint(As[rb][k0 + (lane & 3)]);
                a[mt][1] = __float_as_uint(As[rb + 8][k0 + (lane & 3)]);
                a[mt][2] = __float_as_uint(As[rb][k0 + 4 + (lane & 3)]);
                a[mt][3] = __float_as_uint(As[rb + 8][k0 + 4 + (lane & 3)]);
            }
            #pragma unroll
            for (int nt = 0; nt < 8; ++nt) {
                int nb = wC * 64 + nt * 8 + (lane >> 2);
                bf[nt][0] = __float_as_uint(Ws[k0 + (lane & 3)][nb]);
                bf[nt][1] = __float_as_uint(Ws[k0 + 4 + (lane & 3)][nb]);
            }
            #pragma unroll
            for (int mt = 0; mt < 2; ++mt)
                #pragma unroll
                for (int nt = 0; nt < 8; ++nt)
                    mma_tf32(acc[mt][nt][0], acc[mt][nt][1], acc[mt][nt][2], acc[mt][nt][3],
                             a[mt][0], a[mt][1], a[mt][2], a[mt][3],
                             bf[nt][0], bf[nt][1]);
        }
        __syncthreads();
    }

    // Store PW (fp32) to scratch.
    #pragma unroll
    for (int mt = 0; mt < 2; ++mt) {
        int r0 = mBase + wR * 32 + mt * 16 + (lane >> 2);
        #pragma unroll
        for (int nt = 0; nt < 8; ++nt) {
            int c = nBase + wC * 64 + nt * 8 + ((lane & 3) << 1);
            float2 v01 = make_float2(acc[mt][nt][0], acc[mt][nt][1]);
            float2 v23 = make_float2(acc[mt][nt][2], acc[mt][nt][3]);
            *reinterpret_cast<float2*>(&g_PW[(size_t)r0 * DDIM + c])       = v01;
            *reinterpret_cast<float2*>(&g_PW[(size_t)(r0 + 8) * DDIM + c]) = v23;
        }
    }
}

// ============================================================================
// Kernel 2: logits[b][i][j] = PW[b][i][:] . P[b][j][:] + bias   (GEMM-NT)
// Same tiling. B operand is P rows (K-contiguous), fragments read transposed.
// ============================================================================
__global__ __launch_bounds__(256, 2)
void gemm_logits_kernel(const float* __restrict__ P,
                        const float* __restrict__ bias_ptr,
                        float* __restrict__ C) {
    __shared__ float As[128][36];   // PW rows
    __shared__ float Bs[128][36];   // P rows (j-tile)

    const int t    = threadIdx.x;
    const int lane = t & 31;
    const int warp = t >> 5;
    const int wR   = warp & 3;
    const int wC   = warp >> 2;
    const int batch = blockIdx.z;
    const int iBase = blockIdx.y * 128;
    const int jBase = blockIdx.x * 128;

    const float* A = g_PW + (size_t)batch * NSEQ * DDIM;
    const float* Bm = P   + (size_t)batch * NSEQ * DDIM;
    float* Cb = C + (size_t)batch * NSEQ * NSEQ;

    float acc[2][8][4];
    #pragma unroll
    for (int mt = 0; mt < 2; ++mt)
        #pragma unroll
        for (int nt = 0; nt < 8; ++nt)
            #pragma unroll
            for (int r = 0; r < 4; ++r) acc[mt][nt][r] = 0.f;

    for (int kc = 0; kc < DDIM; kc += 32) {
        #pragma unroll
        for (int p = 0; p < 4; ++p) {
            int id = t + p * 256;
            int r  = id >> 3;
            int c4 = (id & 7) << 2;
            float4 va = *reinterpret_cast<const float4*>(
                &A[(size_t)(iBase + r) * DDIM + kc + c4]);
            As[r][c4 + 0] = __uint_as_float(f2tf(va.x));
            As[r][c4 + 1] = __uint_as_float(f2tf(va.y));
            As[r][c4 + 2] = __uint_as_float(f2tf(va.z));
            As[r][c4 + 3] = __uint_as_float(f2tf(va.w));
            float4 vb = *reinterpret_cast<const float4*>(
                &Bm[(size_t)(jBase + r) * DDIM + kc + c4]);
            Bs[r][c4 + 0] = __uint_as_float(f2tf(vb.x));
            Bs[r][c4 + 1] = __uint_as_float(f2tf(vb.y));
            Bs[r][c4 + 2] = __uint_as_float(f2tf(vb.z));
            Bs[r][c4 + 3] = __uint_as_float(f2tf(vb.w));
        }
        __syncthreads();

        #pragma unroll
        for (int ks = 0; ks < 4; ++ks) {
            const int k0 = ks * 8;
            unsigned a[2][4], bf[8][2];
            #pragma unroll
            for (int mt = 0; mt < 2; ++mt) {
                int rb = wR * 32 + mt * 16 + (lane >> 2);
                a[mt][0] = __float_as_uint(As[rb][k0 + (lane & 3)]);
                a[mt][1] = __float_as_uint(As[rb + 8][k0 + (lane & 3)]);
                a[mt][2] = __float_as_uint(As[rb][k0 + 4 + (lane & 3)]);
                a[mt][3] = __float_as_uint(As[rb + 8][k0 + 4 + (lane & 3)]);
            }
            #pragma unroll
            for (int nt = 0; nt < 8; ++nt) {
                int nb = wC * 64 + nt * 8 + (lane >> 2);   // j row in Bs
                bf[nt][0] = __float_as_uint(Bs[nb][k0 + (lane & 3)]);
                bf[nt][1] = __float_as_uint(Bs[nb][k0 + 4 + (lane & 3)]);
            }
            #pragma unroll
            for (int mt = 0; mt < 2; ++mt)
                #pragma unroll
                for (int nt = 0; nt < 8; ++nt)
                    mma_tf32(acc[mt][nt][0], acc[mt][nt][1], acc[mt][nt][2], acc[mt][nt][3],
                             a[mt][0], a[mt][1], a[mt][2], a[mt][3],
                             bf[nt][0], bf[nt][1]);
        }
        __syncthreads();
    }

    const float bv = __ldg(bias_ptr);

    #pragma unroll
    for (int mt = 0; mt < 2; ++mt) {
        int r0 = iBase + wR * 32 + mt * 16 + (lane >> 2);
        #pragma unroll
        for (int nt = 0; nt < 8; ++nt) {
            int c = jBase + wC * 64 + nt * 8 + ((lane & 3) << 1);
            float2 v01 = make_float2(acc[mt][nt][0] + bv, acc[mt][nt][1] + bv);
            float2 v23 = make_float2(acc[mt][nt][2] + bv, acc[mt][nt][3] + bv);
            *reinterpret_cast<float2*>(&Cb[(size_t)r0 * NSEQ + c])       = v01;
            *reinterpret_cast<float2*>(&Cb[(size_t)(r0 + 8) * NSEQ + c]) = v23;
        }
    }
}

extern "C" void kernel_launch(void* const* d_in, const int* in_sizes, int n_in,
                              void* d_out, int out_size) {
    const float* P  = (const float*)d_in[0];   // [8, 2048, 384]
    const float* W  = (const float*)d_in[1];   // [384, 384]
    const float* bp = (const float*)d_in[2];   // [1]
    float* out = (float*)d_out;                // [8, 2048, 2048]
    (void)in_sizes; (void)n_in; (void)out_size;

    // Kernel 1: PW = P @ W  as one [16384,384] x [384,384]
    dim3 g1(DDIM / 128, (BATCH * NSEQ) / 128, 1);   // (3, 128)
    gemm_pw_kernel<<<g1, 256>>>(P, W);

    // Kernel 2: per-batch logits = PW @ P^T + b
    dim3 g2(NSEQ / 128, NSEQ / 128, BATCH);          // (16, 16, 8)
    gemm_logits_kernel<<<g2, 256>>>(P, bp, out);
}

// round 8
// speedup vs baseline: 1.0424x; 1.0424x over previous
#include <cuda_runtime.h>
#include <cstdint>

#define BATCH 8
#define NSEQ  2048
#define DDIM  384

// Scratch: PW = P @ W (tf32-rounded fp32 bits), and tf32-rounded copy of P.
__device__ float g_PW [BATCH * NSEQ * DDIM];
__device__ float g_Ptf[BATCH * NSEQ * DDIM];

__device__ __forceinline__ unsigned f2tf(float x) {
    unsigned r;
    asm("cvt.rna.tf32.f32 %0, %1;" : "=r"(r) : "f"(x));
    return r;
}

__device__ __forceinline__ uint32_t smem_u32(const void* p) {
    uint32_t a;
    asm("{ .reg .u64 t; cvta.to.shared.u64 t, %1; cvt.u32.u64 %0, t; }" : "=r"(a) : "l"(p));
    return a;
}

__device__ __forceinline__ void cp_async16(uint32_t dst, const void* src) {
    asm volatile("cp.async.cg.shared.global [%0], [%1], 16;" :: "r"(dst), "l"(src) : "memory");
}
#define CP_COMMIT() asm volatile("cp.async.commit_group;" ::: "memory")
#define CP_WAIT2()  asm volatile("cp.async.wait_group 2;" ::: "memory")

__device__ __forceinline__ void mma_tf32(float& d0, float& d1, float& d2, float& d3,
                                         unsigned a0, unsigned a1, unsigned a2, unsigned a3,
                                         unsigned b0, unsigned b1) {
    asm volatile(
        "mma.sync.aligned.m16n8k8.row.col.f32.tf32.tf32.f32 "
        "{%0,%1,%2,%3}, {%4,%5,%6,%7}, {%8,%9}, {%0,%1,%2,%3};"
        : "+f"(d0), "+f"(d1), "+f"(d2), "+f"(d3)
        : "r"(a0), "r"(a1), "r"(a2), "r"(a3), "r"(b0), "r"(b1));
}

// ============================================================================
// Kernel 0: tf32-round P into g_Ptf (elementwise, HBM-bound, ~8us)
// ============================================================================
__global__ void tf32_round_kernel(const float4* __restrict__ in, int n4) {
    float4* out = reinterpret_cast<float4*>(g_Ptf);
    int i = blockIdx.x * blockDim.x + threadIdx.x;
    int stride = gridDim.x * blockDim.x;
    for (; i < n4; i += stride) {
        float4 v = in[i];
        v.x = __uint_as_float(f2tf(v.x));
        v.y = __uint_as_float(f2tf(v.y));
        v.z = __uint_as_float(f2tf(v.z));
        v.w = __uint_as_float(f2tf(v.w));
        out[i] = v;
    }
}

// ============================================================================
// Kernel 1 (proven, R2): PW = P @ W as flat [16384,384]x[384,384].
// Only change: store tf32-rounded values (downstream consumes tf32 anyway).
// ============================================================================
__global__ __launch_bounds__(256, 2)
void gemm_pw_kernel(const float* __restrict__ P, const float* __restrict__ W) {
    __shared__ float As[128][36];
    __shared__ float Ws[32][136];

    const int t    = threadIdx.x;
    const int lane = t & 31;
    const int warp = t >> 5;
    const int wR   = warp & 3;
    const int wC   = warp >> 2;
    const int mBase = blockIdx.y * 128;
    const int nBase = blockIdx.x * 128;

    float acc[2][8][4];
    #pragma unroll
    for (int mt = 0; mt < 2; ++mt)
        #pragma unroll
        for (int nt = 0; nt < 8; ++nt)
            #pragma unroll
            for (int r = 0; r < 4; ++r) acc[mt][nt][r] = 0.f;

    for (int kc = 0; kc < DDIM; kc += 32) {
        #pragma unroll
        for (int p = 0; p < 4; ++p) {
            int id = t + p * 256;
            int r  = id >> 3;
            int c4 = (id & 7) << 2;
            float4 v = *reinterpret_cast<const float4*>(
                &P[(size_t)(mBase + r) * DDIM + kc + c4]);
            As[r][c4 + 0] = __uint_as_float(f2tf(v.x));
            As[r][c4 + 1] = __uint_as_float(f2tf(v.y));
            As[r][c4 + 2] = __uint_as_float(f2tf(v.z));
            As[r][c4 + 3] = __uint_as_float(f2tf(v.w));
        }
        #pragma unroll
        for (int p = 0; p < 4; ++p) {
            int id = t + p * 256;
            int r  = id >> 5;
            int c4 = (id & 31) << 2;
            float4 v = *reinterpret_cast<const float4*>(
                &W[(size_t)(kc + r) * DDIM + nBase + c4]);
            Ws[r][c4 + 0] = __uint_as_float(f2tf(v.x));
            Ws[r][c4 + 1] = __uint_as_float(f2tf(v.y));
            Ws[r][c4 + 2] = __uint_as_float(f2tf(v.z));
            Ws[r][c4 + 3] = __uint_as_float(f2tf(v.w));
        }
        __syncthreads();

        #pragma unroll
        for (int ks = 0; ks < 4; ++ks) {
            const int k0 = ks * 8;
            unsigned a[2][4], bf[8][2];
            #pragma unroll
            for (int mt = 0; mt < 2; ++mt) {
                int rb = wR * 32 + mt * 16 + (lane >> 2);
                a[mt][0] = __float_as_uint(As[rb][k0 + (lane & 3)]);
                a[mt][1] = __float_as_uint(As[rb + 8][k0 + (lane & 3)]);
                a[mt][2] = __float_as_uint(As[rb][k0 + 4 + (lane & 3)]);
                a[mt][3] = __float_as_uint(As[rb + 8][k0 + 4 + (lane & 3)]);
            }
            #pragma unroll
            for (int nt = 0; nt < 8; ++nt) {
                int nb = wC * 64 + nt * 8 + (lane >> 2);
                bf[nt][0] = __float_as_uint(Ws[k0 + (lane & 3)][nb]);
                bf[nt][1] = __float_as_uint(Ws[k0 + 4 + (lane & 3)][nb]);
            }
            #pragma unroll
            for (int mt = 0; mt < 2; ++mt)
                #pragma unroll
                for (int nt = 0; nt < 8; ++nt)
                    mma_tf32(acc[mt][nt][0], acc[mt][nt][1], acc[mt][nt][2], acc[mt][nt][3],
                             a[mt][0], a[mt][1], a[mt][2], a[mt][3],
                             bf[nt][0], bf[nt][1]);
        }
        __syncthreads();
    }

    #pragma unroll
    for (int mt = 0; mt < 2; ++mt) {
        int r0 = mBase + wR * 32 + mt * 16 + (lane >> 2);
        #pragma unroll
        for (int nt = 0; nt < 8; ++nt) {
            int c = nBase + wC * 64 + nt * 8 + ((lane & 3) << 1);
            float2 v01 = make_float2(__uint_as_float(f2tf(acc[mt][nt][0])),
                                     __uint_as_float(f2tf(acc[mt][nt][1])));
            float2 v23 = make_float2(__uint_as_float(f2tf(acc[mt][nt][2])),
                                     __uint_as_float(f2tf(acc[mt][nt][3])));
            *reinterpret_cast<float2*>(&g_PW[(size_t)r0 * DDIM + c])       = v01;
            *reinterpret_cast<float2*>(&g_PW[(size_t)(r0 + 8) * DDIM + c]) = v23;
        }
    }
}

// ============================================================================
// Kernel 2: logits[b] = PW[b] @ P[b]^T + bias   (GEMM-NT, tf32 mma.sync)
// CTA tile 256(M) x 128(N), 8 warps (4x2) of 64x64, BK=32,
// 3-stage cp.async.cg pipeline (operands pre-rounded to tf32 in gmem).
// ============================================================================
#define BM2 256
#define BN2 128
#define BK2 32
#define NCHUNK (DDIM / BK2)            // 12
#define AROW_F 36                      // padded row (floats)
#define A_STG_F (BM2 * AROW_F)         // 9216 floats
#define B_STG_F (BN2 * AROW_F)         // 4608 floats
#define STG_F   (A_STG_F + B_STG_F)    // 13824 floats
#define SMEM_K2_BYTES (3 * STG_F * 4)  // 165888 B

__global__ __launch_bounds__(256, 1)
void gemm_logits_k2(const float* __restrict__ bias_ptr, float* __restrict__ C) {
    extern __shared__ float sm[];
    const uint32_t sm_base = smem_u32(sm);

    const int t    = threadIdx.x;
    const int lane = t & 31;
    const int warp = t >> 5;
    const int wR   = warp & 3;         // 0..3 : m 64-blocks
    const int wC   = warp >> 2;        // 0..1 : n 64-blocks
    const int batch = blockIdx.z;
    const int iBase = blockIdx.y * BM2;
    const int jBase = blockIdx.x * BN2;

    const float* Ag = g_PW  + (size_t)batch * NSEQ * DDIM;   // tf32-rounded
    const float* Bg = g_Ptf + (size_t)batch * NSEQ * DDIM;   // tf32-rounded
    float* Cb = C + (size_t)batch * NSEQ * NSEQ;

    float acc[4][8][4];
    #pragma unroll
    for (int mt = 0; mt < 4; ++mt)
        #pragma unroll
        for (int nt = 0; nt < 8; ++nt)
            #pragma unroll
            for (int r = 0; r < 4; ++r) acc[mt][nt][r] = 0.f;

    // ---- async fill of one chunk into stage s ----
    auto fill = [&](int c, int s) {
        const int kc = c * BK2;
        const uint32_t a_u32 = sm_base + (uint32_t)(s * STG_F * 4);
        const uint32_t b_u32 = a_u32 + A_STG_F * 4;
        #pragma unroll
        for (int p = 0; p < 8; ++p) {              // A: 256x32 -> 2048 f4
            int id = t + p * 256;
            int r  = id >> 3;
            int c4 = (id & 7) << 2;
            cp_async16(a_u32 + (uint32_t)(r * AROW_F + c4) * 4,
                       &Ag[(size_t)(iBase + r) * DDIM + kc + c4]);
        }
        #pragma unroll
        for (int p = 0; p < 4; ++p) {              // B: 128x32 -> 1024 f4
            int id = t + p * 256;
            int r  = id >> 3;
            int c4 = (id & 7) << 2;
            cp_async16(b_u32 + (uint32_t)(r * AROW_F + c4) * 4,
                       &Bg[(size_t)(jBase + r) * DDIM + kc + c4]);
        }
    };

    fill(0, 0); CP_COMMIT();
    fill(1, 1); CP_COMMIT();

    for (int c = 0; c < NCHUNK; ++c) {
        if (c + 2 < NCHUNK) fill(c + 2, (c + 2) % 3);
        CP_COMMIT();
        CP_WAIT2();
        __syncthreads();

        const float* As = sm + (c % 3) * STG_F;
        const float* Bs = As + A_STG_F;

        #pragma unroll
        for (int ks = 0; ks < 4; ++ks) {
            const int k0 = ks * 8 + (lane & 3);
            unsigned a[4][4], bf[8][2];
            #pragma unroll
            for (int mt = 0; mt < 4; ++mt) {
                const float* ap = As + (wR * 64 + mt * 16 + (lane >> 2)) * AROW_F + k0;
                a[mt][0] = __float_as_uint(ap[0]);
                a[mt][1] = __float_as_uint(ap[8 * AROW_F]);
                a[mt][2] = __float_as_uint(ap[4]);
                a[mt][3] = __float_as_uint(ap[8 * AROW_F + 4]);
            }
            #pragma unroll
            for (int nt = 0; nt < 8; ++nt) {
                const float* bp = Bs + (wC * 64 + nt * 8 + (lane >> 2)) * AROW_F + k0;
                bf[nt][0] = __float_as_uint(bp[0]);
                bf[nt][1] = __float_as_uint(bp[4]);
            }
            #pragma unroll
            for (int mt = 0; mt < 4; ++mt)
                #pragma unroll
                for (int nt = 0; nt < 8; ++nt)
                    mma_tf32(acc[mt][nt][0], acc[mt][nt][1], acc[mt][nt][2], acc[mt][nt][3],
                             a[mt][0], a[mt][1], a[mt][2], a[mt][3],
                             bf[nt][0], bf[nt][1]);
        }
        __syncthreads();
    }

    const float bv = __ldg(bias_ptr);
    #pragma unroll
    for (int mt = 0; mt < 4; ++mt) {
        int r0 = iBase + wR * 64 + mt * 16 + (lane >> 2);
        #pragma unroll
        for (int nt = 0; nt < 8; ++nt) {
            int cc = jBase + wC * 64 + nt * 8 + ((lane & 3) << 1);
            float2 v01 = make_float2(acc[mt][nt][0] + bv, acc[mt][nt][1] + bv);
            float2 v23 = make_float2(acc[mt][nt][2] + bv, acc[mt][nt][3] + bv);
            *reinterpret_cast<float2*>(&Cb[(size_t)r0 * NSEQ + cc])       = v01;
            *reinterpret_cast<float2*>(&Cb[(size_t)(r0 + 8) * NSEQ + cc]) = v23;
        }
    }
}

extern "C" void kernel_launch(void* const* d_in, const int* in_sizes, int n_in,
                              void* d_out, int out_size) {
    const float* P  = (const float*)d_in[0];   // [8, 2048, 384]
    const float* W  = (const float*)d_in[1];   // [384, 384]
    const float* bp = (const float*)d_in[2];   // [1]
    float* out = (float*)d_out;                // [8, 2048, 2048]
    (void)in_sizes; (void)n_in; (void)out_size;

    static bool attr_set = false;
    if (!attr_set) {
        cudaFuncSetAttribute(gemm_logits_k2,
                             cudaFuncAttributeMaxDynamicSharedMemorySize, SMEM_K2_BYTES);
        attr_set = true;
    }

    // Kernel 0: tf32-round P -> g_Ptf
    int n4 = BATCH * NSEQ * DDIM / 4;                      // 1572864
    tf32_round_kernel<<<2048, 256>>>(reinterpret_cast<const float4*>(P), n4);

    // Kernel 1: PW = P @ W (tf32-rounded at store)
    dim3 g1(DDIM / 128, (BATCH * NSEQ) / 128, 1);          // (3, 128)
    gemm_pw_kernel<<<g1, 256>>>(P, W);

    // Kernel 2: per-batch logits = PW @ P^T + b
    dim3 g2(NSEQ / BN2, NSEQ / BM2, BATCH);                // (16, 8, 8)
    gemm_logits_k2<<<g2, 256, SMEM_K2_BYTES>>>(bp, out);
}

// round 9
// speedup vs baseline: 1.5668x; 1.5031x over previous
#include <cuda_runtime.h>
#include <cuda_fp16.h>
#include <cstdint>

#define BATCH 8
#define NSEQ  2048
#define DDIM  384

// Scratch: PW (fp16), fp16 copy of P. No device-side allocation.
__device__ __half g_PW   [BATCH * NSEQ * DDIM];
__device__ __half g_Phalf[BATCH * NSEQ * DDIM];

__device__ __forceinline__ unsigned f2tf(float x) {
    unsigned r;
    asm("cvt.rna.tf32.f32 %0, %1;" : "=r"(r) : "f"(x));
    return r;
}

__device__ __forceinline__ uint32_t smem_u32(const void* p) {
    uint32_t a;
    asm("{ .reg .u64 t; cvta.to.shared.u64 t, %1; cvt.u32.u64 %0, t; }" : "=r"(a) : "l"(p));
    return a;
}

__device__ __forceinline__ void cp_async16(uint32_t dst, const void* src) {
    asm volatile("cp.async.cg.shared.global [%0], [%1], 16;" :: "r"(dst), "l"(src) : "memory");
}
#define CP_COMMIT() asm volatile("cp.async.commit_group;" ::: "memory")
#define CP_WAIT2()  asm volatile("cp.async.wait_group 2;" ::: "memory")

// tf32 mma (kernel 1, proven)
__device__ __forceinline__ void mma_tf32(float& d0, float& d1, float& d2, float& d3,
                                         unsigned a0, unsigned a1, unsigned a2, unsigned a3,
                                         unsigned b0, unsigned b1) {
    asm volatile(
        "mma.sync.aligned.m16n8k8.row.col.f32.tf32.tf32.f32 "
        "{%0,%1,%2,%3}, {%4,%5,%6,%7}, {%8,%9}, {%0,%1,%2,%3};"
        : "+f"(d0), "+f"(d1), "+f"(d2), "+f"(d3)
        : "r"(a0), "r"(a1), "r"(a2), "r"(a3), "r"(b0), "r"(b1));
}

// fp16 mma m16n8k16, fp32 accumulate (kernel 2)
__device__ __forceinline__ void mma_f16(float& d0, float& d1, float& d2, float& d3,
                                        unsigned a0, unsigned a1, unsigned a2, unsigned a3,
                                        unsigned b0, unsigned b1) {
    asm volatile(
        "mma.sync.aligned.m16n8k16.row.col.f32.f16.f16.f32 "
        "{%0,%1,%2,%3}, {%4,%5,%6,%7}, {%8,%9}, {%0,%1,%2,%3};"
        : "+f"(d0), "+f"(d1), "+f"(d2), "+f"(d3)
        : "r"(a0), "r"(a1), "r"(a2), "r"(a3), "r"(b0), "r"(b1));
}

// ============================================================================
// Kernel 0: P (fp32) -> g_Phalf (fp16), elementwise, HBM-bound
// ============================================================================
__global__ void cvt_half_kernel(const float4* __restrict__ in, int n4) {
    int i = blockIdx.x * blockDim.x + threadIdx.x;
    int stride = gridDim.x * blockDim.x;
    for (; i < n4; i += stride) {
        float4 v = in[i];
        __half2 h0 = __floats2half2_rn(v.x, v.y);
        __half2 h1 = __floats2half2_rn(v.z, v.w);
        uint2 o;
        o.x = *reinterpret_cast<unsigned*>(&h0);
        o.y = *reinterpret_cast<unsigned*>(&h1);
        *reinterpret_cast<uint2*>(&g_Phalf[(size_t)i * 4]) = o;
    }
}

// ============================================================================
// Kernel 1 (tf32, proven): PW = P @ W as flat [16384,384]x[384,384].
// Output stored as fp16 (consumer is an 11-bit-mantissa mma anyway).
// ============================================================================
__global__ __launch_bounds__(256, 2)
void gemm_pw_kernel(const float* __restrict__ P, const float* __restrict__ W) {
    __shared__ float As[128][36];
    __shared__ float Ws[32][136];

    const int t    = threadIdx.x;
    const int lane = t & 31;
    const int warp = t >> 5;
    const int wR   = warp & 3;
    const int wC   = warp >> 2;
    const int mBase = blockIdx.y * 128;
    const int nBase = blockIdx.x * 128;

    float acc[2][8][4];
    #pragma unroll
    for (int mt = 0; mt < 2; ++mt)
        #pragma unroll
        for (int nt = 0; nt < 8; ++nt)
            #pragma unroll
            for (int r = 0; r < 4; ++r) acc[mt][nt][r] = 0.f;

    for (int kc = 0; kc < DDIM; kc += 32) {
        #pragma unroll
        for (int p = 0; p < 4; ++p) {
            int id = t + p * 256;
            int r  = id >> 3;
            int c4 = (id & 7) << 2;
            float4 v = *reinterpret_cast<const float4*>(
                &P[(size_t)(mBase + r) * DDIM + kc + c4]);
            As[r][c4 + 0] = __uint_as_float(f2tf(v.x));
            As[r][c4 + 1] = __uint_as_float(f2tf(v.y));
            As[r][c4 + 2] = __uint_as_float(f2tf(v.z));
            As[r][c4 + 3] = __uint_as_float(f2tf(v.w));
        }
        #pragma unroll
        for (int p = 0; p < 4; ++p) {
            int id = t + p * 256;
            int r  = id >> 5;
            int c4 = (id & 31) << 2;
            float4 v = *reinterpret_cast<const float4*>(
                &W[(size_t)(kc + r) * DDIM + nBase + c4]);
            Ws[r][c4 + 0] = __uint_as_float(f2tf(v.x));
            Ws[r][c4 + 1] = __uint_as_float(f2tf(v.y));
            Ws[r][c4 + 2] = __uint_as_float(f2tf(v.z));
            Ws[r][c4 + 3] = __uint_as_float(f2tf(v.w));
        }
        __syncthreads();

        #pragma unroll
        for (int ks = 0; ks < 4; ++ks) {
            const int k0 = ks * 8;
            unsigned a[2][4], bf[8][2];
            #pragma unroll
            for (int mt = 0; mt < 2; ++mt) {
                int rb = wR * 32 + mt * 16 + (lane >> 2);
                a[mt][0] = __float_as_uint(As[rb][k0 + (lane & 3)]);
                a[mt][1] = __float_as_uint(As[rb + 8][k0 + (lane & 3)]);
                a[mt][2] = __float_as_uint(As[rb][k0 + 4 + (lane & 3)]);
                a[mt][3] = __float_as_uint(As[rb + 8][k0 + 4 + (lane & 3)]);
            }
            #pragma unroll
            for (int nt = 0; nt < 8; ++nt) {
                int nb = wC * 64 + nt * 8 + (lane >> 2);
                bf[nt][0] = __float_as_uint(Ws[k0 + (lane & 3)][nb]);
                bf[nt][1] = __float_as_uint(Ws[k0 + 4 + (lane & 3)][nb]);
            }
            #pragma unroll
            for (int mt = 0; mt < 2; ++mt)
                #pragma unroll
                for (int nt = 0; nt < 8; ++nt)
                    mma_tf32(acc[mt][nt][0], acc[mt][nt][1], acc[mt][nt][2], acc[mt][nt][3],
                             a[mt][0], a[mt][1], a[mt][2], a[mt][3],
                             bf[nt][0], bf[nt][1]);
        }
        __syncthreads();
    }

    // Store PW as fp16
    #pragma unroll
    for (int mt = 0; mt < 2; ++mt) {
        int r0 = mBase + wR * 32 + mt * 16 + (lane >> 2);
        #pragma unroll
        for (int nt = 0; nt < 8; ++nt) {
            int c = nBase + wC * 64 + nt * 8 + ((lane & 3) << 1);
            __half2 h01 = __floats2half2_rn(acc[mt][nt][0], acc[mt][nt][1]);
            __half2 h23 = __floats2half2_rn(acc[mt][nt][2], acc[mt][nt][3]);
            *reinterpret_cast<__half2*>(&g_PW[(size_t)r0 * DDIM + c])       = h01;
            *reinterpret_cast<__half2*>(&g_PW[(size_t)(r0 + 8) * DDIM + c]) = h23;
        }
    }
}

// ============================================================================
// Kernel 2: logits[b] = PW[b] @ P[b]^T + bias  (fp16 m16n8k16, fp32 acc)
// CTA 256(M) x 128(N), 8 warps (4x2) of 64x64, BK=64, 3-stage cp.async.
// SMEM rows: 64 fp16 = 128B data padded to 144B -> bank = (4r+q)%32, conflict-free.
// ============================================================================
#define BM2 256
#define BN2 128
#define BK2 64
#define NCHUNK (DDIM / BK2)            // 6
#define ROWB 144                       // padded row bytes (128 data + 16 pad)
#define A_STG (BM2 * ROWB)             // 36864 B
#define B_STG (BN2 * ROWB)             // 18432 B
#define STG   (A_STG + B_STG)          // 55296 B
#define SMEM_K2_BYTES (3 * STG)        // 165888 B

__global__ __launch_bounds__(256, 1)
void gemm_logits_k2(const float* __restrict__ bias_ptr, float* __restrict__ C) {
    extern __shared__ char sm[];
    const uint32_t sm_base = smem_u32(sm);

    const int t    = threadIdx.x;
    const int lane = t & 31;
    const int warp = t >> 5;
    const int wR   = warp & 3;         // m 64-block
    const int wC   = warp >> 2;        // n 64-block
    const int batch = blockIdx.z;
    const int iBase = blockIdx.y * BM2;
    const int jBase = blockIdx.x * BN2;

    const __half* Ag = g_PW    + (size_t)batch * NSEQ * DDIM;
    const __half* Bg = g_Phalf + (size_t)batch * NSEQ * DDIM;
    float* Cb = C + (size_t)batch * NSEQ * NSEQ;

    float acc[4][8][4];
    #pragma unroll
    for (int mt = 0; mt < 4; ++mt)
        #pragma unroll
        for (int nt = 0; nt < 8; ++nt)
            #pragma unroll
            for (int r = 0; r < 4; ++r) acc[mt][nt][r] = 0.f;

    auto fill = [&](int c, int s) {
        const int kc = c * BK2;                       // half index
        const uint32_t a_u32 = sm_base + (uint32_t)(s * STG);
        const uint32_t b_u32 = a_u32 + A_STG;
        #pragma unroll
        for (int p = 0; p < 8; ++p) {                 // A: 256 rows x 128B
            int id  = t + p * 256;                    // 0..2047
            int r   = id >> 3;
            int seg = id & 7;
            cp_async16(a_u32 + (uint32_t)(r * ROWB + seg * 16),
                       &Ag[(size_t)(iBase + r) * DDIM + kc + seg * 8]);
        }
        #pragma unroll
        for (int p = 0; p < 4; ++p) {                 // B: 128 rows x 128B
            int id  = t + p * 256;                    // 0..1023
            int r   = id >> 3;
            int seg = id & 7;
            cp_async16(b_u32 + (uint32_t)(r * ROWB + seg * 16),
                       &Bg[(size_t)(jBase + r) * DDIM + kc + seg * 8]);
        }
    };

    fill(0, 0); CP_COMMIT();
    fill(1, 1); CP_COMMIT();

    for (int c = 0; c < NCHUNK; ++c) {
        if (c + 2 < NCHUNK) fill(c + 2, (c + 2) % 3);
        CP_COMMIT();
        CP_WAIT2();
        __syncthreads();

        const char* As = sm + (c % 3) * STG;
        const char* Bs = As + A_STG;

        #pragma unroll
        for (int ks = 0; ks < 4; ++ks) {              // 4 x K=16
            const int cb = ks * 32 + (lane & 3) * 4;  // byte col in row
            unsigned a[4][4], bf[8][2];
            #pragma unroll
            for (int mt = 0; mt < 4; ++mt) {
                int rA = wR * 64 + mt * 16 + (lane >> 2);
                const char* ap = As + rA * ROWB + cb;
                a[mt][0] = *reinterpret_cast<const unsigned*>(ap);
                a[mt][1] = *reinterpret_cast<const unsigned*>(ap + 8 * ROWB);
                a[mt][2] = *reinterpret_cast<const unsigned*>(ap + 16);
                a[mt][3] = *reinterpret_cast<const unsigned*>(ap + 8 * ROWB + 16);
            }
            #pragma unroll
            for (int nt = 0; nt < 8; ++nt) {
                int rB = wC * 64 + nt * 8 + (lane >> 2);
                const char* bp = Bs + rB * ROWB + cb;
                bf[nt][0] = *reinterpret_cast<const unsigned*>(bp);
                bf[nt][1] = *reinterpret_cast<const unsigned*>(bp + 16);
            }
            #pragma unroll
            for (int mt = 0; mt < 4; ++mt)
                #pragma unroll
                for (int nt = 0; nt < 8; ++nt)
                    mma_f16(acc[mt][nt][0], acc[mt][nt][1], acc[mt][nt][2], acc[mt][nt][3],
                            a[mt][0], a[mt][1], a[mt][2], a[mt][3],
                            bf[nt][0], bf[nt][1]);
        }
        __syncthreads();
    }

    const float bv = __ldg(bias_ptr);
    #pragma unroll
    for (int mt = 0; mt < 4; ++mt) {
        int r0 = iBase + wR * 64 + mt * 16 + (lane >> 2);
        #pragma unroll
        for (int nt = 0; nt < 8; ++nt) {
            int cc = jBase + wC * 64 + nt * 8 + ((lane & 3) << 1);
            float2 v01 = make_float2(acc[mt][nt][0] + bv, acc[mt][nt][1] + bv);
            float2 v23 = make_float2(acc[mt][nt][2] + bv, acc[mt][nt][3] + bv);
            *reinterpret_cast<float2*>(&Cb[(size_t)r0 * NSEQ + cc])       = v01;
            *reinterpret_cast<float2*>(&Cb[(size_t)(r0 + 8) * NSEQ + cc]) = v23;
        }
    }
}

extern "C" void kernel_launch(void* const* d_in, const int* in_sizes, int n_in,
                              void* d_out, int out_size) {
    const float* P  = (const float*)d_in[0];   // [8, 2048, 384]
    const float* W  = (const float*)d_in[1];   // [384, 384]
    const float* bp = (const float*)d_in[2];   // [1]
    float* out = (float*)d_out;                // [8, 2048, 2048]
    (void)in_sizes; (void)n_in; (void)out_size;

    static bool attr_set = false;
    if (!attr_set) {
        cudaFuncSetAttribute(gemm_logits_k2,
                             cudaFuncAttributeMaxDynamicSharedMemorySize, SMEM_K2_BYTES);
        attr_set = true;
    }

    // Kernel 0: P -> fp16 copy
    int n4 = BATCH * NSEQ * DDIM / 4;                      // 1572864
    cvt_half_kernel<<<2048, 256>>>(reinterpret_cast<const float4*>(P), n4);

    // Kernel 1: PW = P @ W (tf32 mma, fp16 store)
    dim3 g1(DDIM / 128, (BATCH * NSEQ) / 128, 1);          // (3, 128)
    gemm_pw_kernel<<<g1, 256>>>(P, W);

    // Kernel 2: per-batch logits = PW @ P^T + b (fp16 mma)
    dim3 g2(NSEQ / BN2, NSEQ / BM2, BATCH);                // (16, 8, 8)
    gemm_logits_k2<<<g2, 256, SMEM_K2_BYTES>>>(bp, out);
}

// round 10
// speedup vs baseline: 1.7297x; 1.1039x over previous
#include <cuda_runtime.h>
#include <cuda_fp16.h>
#include <cstdint>

#define BATCH 8
#define NSEQ  2048
#define DDIM  384

// Scratch (device globals, no allocation): fp16 P copy, fp16 W^T, fp16 PW.
__device__ __half g_Phalf[BATCH * NSEQ * DDIM];
__device__ __half g_WT   [DDIM * DDIM];
__device__ __half g_PW   [BATCH * NSEQ * DDIM];

__device__ __forceinline__ uint32_t smem_u32(const void* p) {
    uint32_t a;
    asm("{ .reg .u64 t; cvta.to.shared.u64 t, %1; cvt.u32.u64 %0, t; }" : "=r"(a) : "l"(p));
    return a;
}
__device__ __forceinline__ void cp_async16(uint32_t dst, const void* src) {
    asm volatile("cp.async.cg.shared.global [%0], [%1], 16;" :: "r"(dst), "l"(src) : "memory");
}
#define CP_COMMIT() asm volatile("cp.async.commit_group;" ::: "memory")
#define CP_WAIT2()  asm volatile("cp.async.wait_group 2;" ::: "memory")

__device__ __forceinline__ void mma_f16(float& d0, float& d1, float& d2, float& d3,
                                        unsigned a0, unsigned a1, unsigned a2, unsigned a3,
                                        unsigned b0, unsigned b1) {
    asm volatile(
        "mma.sync.aligned.m16n8k16.row.col.f32.f16.f16.f32 "
        "{%0,%1,%2,%3}, {%4,%5,%6,%7}, {%8,%9}, {%0,%1,%2,%3};"
        : "+f"(d0), "+f"(d1), "+f"(d2), "+f"(d3)
        : "r"(a0), "r"(a1), "r"(a2), "r"(a3), "r"(b0), "r"(b1));
}

__device__ __forceinline__ void ldsm4(unsigned r[4], uint32_t addr) {
    asm volatile("ldmatrix.sync.aligned.m8n8.x4.shared.b16 {%0,%1,%2,%3}, [%4];"
        : "=r"(r[0]), "=r"(r[1]), "=r"(r[2]), "=r"(r[3]) : "r"(addr));
}

// ============================================================================
// Kernel 0a: P (fp32) -> g_Phalf
// ============================================================================
__global__ void cvt_half_kernel(const float4* __restrict__ in, int n4) {
    int i = blockIdx.x * blockDim.x + threadIdx.x;
    int stride = gridDim.x * blockDim.x;
    for (; i < n4; i += stride) {
        float4 v = in[i];
        __half2 h0 = __floats2half2_rn(v.x, v.y);
        __half2 h1 = __floats2half2_rn(v.z, v.w);
        uint2 o;
        o.x = *reinterpret_cast<unsigned*>(&h0);
        o.y = *reinterpret_cast<unsigned*>(&h1);
        *reinterpret_cast<uint2*>(&g_Phalf[(size_t)i * 4]) = o;
    }
}

// ============================================================================
// Kernel 0b: W (fp32 [k][n]) -> g_WT (fp16 [n][k])
// ============================================================================
__global__ void wtrans_kernel(const float* __restrict__ W) {
    int idx = blockIdx.x * blockDim.x + threadIdx.x;
    if (idx < DDIM * DDIM) {
        int k = idx / DDIM, n = idx % DDIM;
        g_WT[(size_t)n * DDIM + k] = __float2half_rn(W[idx]);
    }
}

// ============================================================================
// Shared GEMM-NT mainloop (fp16 m16n8k16, fp32 acc):
// C_tile[256x128] = A[iBase..+256][0..384) . B[jBase..+128][0..384)^T
// 8 warps (4x2) of 64x64, BK=64, 3-stage cp.async, ldmatrix fragments.
// ============================================================================
#define BM2 256
#define BN2 128
#define BK2 64
#define NCHUNK (DDIM / BK2)            // 6
#define ROWB 144                       // 128B data + 16B pad; conflict-free LDSM
#define A_STG (BM2 * ROWB)             // 36864 B
#define B_STG (BN2 * ROWB)             // 18432 B
#define STG   (A_STG + B_STG)          // 55296 B
#define SMEM_BYTES (3 * STG)           // 165888 B

__device__ __forceinline__ void gemm_nt_mainloop(
    const __half* __restrict__ Ag, const __half* __restrict__ Bg,
    char* sm, int iBase, int jBase, float acc[4][8][4])
{
    const uint32_t sm_base = smem_u32(sm);
    const int t    = threadIdx.x;
    const int lane = t & 31;
    const int warp = t >> 5;
    const int wR   = warp & 3;
    const int wC   = warp >> 2;

    auto fill = [&](int c, int s) {
        const int kc = c * BK2;
        const uint32_t a_u32 = sm_base + (uint32_t)(s * STG);
        const uint32_t b_u32 = a_u32 + A_STG;
        #pragma unroll
        for (int p = 0; p < 8; ++p) {
            int id  = t + p * 256;
            int r   = id >> 3;
            int seg = id & 7;
            cp_async16(a_u32 + (uint32_t)(r * ROWB + seg * 16),
                       &Ag[(size_t)(iBase + r) * DDIM + kc + seg * 8]);
        }
        #pragma unroll
        for (int p = 0; p < 4; ++p) {
            int id  = t + p * 256;
            int r   = id >> 3;
            int seg = id & 7;
            cp_async16(b_u32 + (uint32_t)(r * ROWB + seg * 16),
                       &Bg[(size_t)(jBase + r) * DDIM + kc + seg * 8]);
        }
    };

    fill(0, 0); CP_COMMIT();
    fill(1, 1); CP_COMMIT();

    const int g  = lane >> 3;
    const int rr = lane & 7;
    // A-fragment ldsm address offset: matrices (r0k0, r8k0, r0k8, r8k8)
    const uint32_t aoff = (uint32_t)(rr * ROWB + (g & 1) * (8 * ROWB) + (g >> 1) * 16);
    // B-fragment ldsm address offset: matrices (n0k0, n0k8, n8k0, n8k8)
    const uint32_t boff = (uint32_t)(rr * ROWB + (g >> 1) * (8 * ROWB) + (g & 1) * 16);

    for (int c = 0; c < NCHUNK; ++c) {
        if (c + 2 < NCHUNK) fill(c + 2, (c + 2) % 3);
        CP_COMMIT();
        CP_WAIT2();
        __syncthreads();

        const uint32_t As = sm_base + (uint32_t)((c % 3) * STG);
        const uint32_t Bs = As + A_STG;
        const uint32_t Abase = As + (uint32_t)(wR * 64 * ROWB) + aoff;
        const uint32_t Bbase = Bs + (uint32_t)(wC * 64 * ROWB) + boff;

        #pragma unroll
        for (int ks = 0; ks < 4; ++ks) {
            const uint32_t cb = ks * 32;
            unsigned a[4][4], bf[8][2];
            #pragma unroll
            for (int mt = 0; mt < 4; ++mt)
                ldsm4(a[mt], Abase + (uint32_t)(mt * 16 * ROWB) + cb);
            #pragma unroll
            for (int np = 0; np < 4; ++np) {
                unsigned bq[4];
                ldsm4(bq, Bbase + (uint32_t)(np * 16 * ROWB) + cb);
                bf[2 * np][0]     = bq[0];
                bf[2 * np][1]     = bq[1];
                bf[2 * np + 1][0] = bq[2];
                bf[2 * np + 1][1] = bq[3];
            }
            #pragma unroll
            for (int mt = 0; mt < 4; ++mt)
                #pragma unroll
                for (int nt = 0; nt < 8; ++nt)
                    mma_f16(acc[mt][nt][0], acc[mt][nt][1], acc[mt][nt][2], acc[mt][nt][3],
                            a[mt][0], a[mt][1], a[mt][2], a[mt][3],
                            bf[nt][0], bf[nt][1]);
        }
        __syncthreads();
    }
}

// ============================================================================
// Kernel 1: PW = P @ W (fp16 NT vs W^T), fp16 store to g_PW
// ============================================================================
__global__ __launch_bounds__(256, 1)
void gemm_pw_f16(int dummy) {
    extern __shared__ char sm[];
    const int lane = threadIdx.x & 31;
    const int warp = threadIdx.x >> 5;
    const int wR   = warp & 3;
    const int wC   = warp >> 2;
    const int iBase = blockIdx.y * BM2;        // 0..16384
    const int jBase = blockIdx.x * BN2;        // 0..384

    float acc[4][8][4];
    #pragma unroll
    for (int mt = 0; mt < 4; ++mt)
        #pragma unroll
        for (int nt = 0; nt < 8; ++nt)
            #pragma unroll
            for (int r = 0; r < 4; ++r) acc[mt][nt][r] = 0.f;

    gemm_nt_mainloop(g_Phalf, g_WT, sm, iBase, jBase, acc);

    #pragma unroll
    for (int mt = 0; mt < 4; ++mt) {
        int r0 = iBase + wR * 64 + mt * 16 + (lane >> 2);
        #pragma unroll
        for (int nt = 0; nt < 8; ++nt) {
            int cc = jBase + wC * 64 + nt * 8 + ((lane & 3) << 1);
            __half2 h01 = __floats2half2_rn(acc[mt][nt][0], acc[mt][nt][1]);
            __half2 h23 = __floats2half2_rn(acc[mt][nt][2], acc[mt][nt][3]);
            *reinterpret_cast<__half2*>(&g_PW[(size_t)r0 * DDIM + cc])       = h01;
            *reinterpret_cast<__half2*>(&g_PW[(size_t)(r0 + 8) * DDIM + cc]) = h23;
        }
    }
}

// ============================================================================
// Kernel 2: logits[b] = PW[b] @ P[b]^T + bias, fp32 store
// ============================================================================
__global__ __launch_bounds__(256, 1)
void gemm_logits_k2(const float* __restrict__ bias_ptr, float* __restrict__ C) {
    extern __shared__ char sm[];
    const int lane = threadIdx.x & 31;
    const int warp = threadIdx.x >> 5;
    const int wR   = warp & 3;
    const int wC   = warp >> 2;
    const int batch = blockIdx.z;
    const int iBase = blockIdx.y * BM2;
    const int jBase = blockIdx.x * BN2;

    const __half* Ag = g_PW    + (size_t)batch * NSEQ * DDIM;
    const __half* Bg = g_Phalf + (size_t)batch * NSEQ * DDIM;
    float* Cb = C + (size_t)batch * NSEQ * NSEQ;

    float acc[4][8][4];
    #pragma unroll
    for (int mt = 0; mt < 4; ++mt)
        #pragma unroll
        for (int nt = 0; nt < 8; ++nt)
            #pragma unroll
            for (int r = 0; r < 4; ++r) acc[mt][nt][r] = 0.f;

    gemm_nt_mainloop(Ag, Bg, sm, iBase, jBase, acc);

    const float bv = __ldg(bias_ptr);
    #pragma unroll
    for (int mt = 0; mt < 4; ++mt) {
        int r0 = iBase + wR * 64 + mt * 16 + (lane >> 2);
        #pragma unroll
        for (int nt = 0; nt < 8; ++nt) {
            int cc = jBase + wC * 64 + nt * 8 + ((lane & 3) << 1);
            float2 v01 = make_float2(acc[mt][nt][0] + bv, acc[mt][nt][1] + bv);
            float2 v23 = make_float2(acc[mt][nt][2] + bv, acc[mt][nt][3] + bv);
            *reinterpret_cast<float2*>(&Cb[(size_t)r0 * NSEQ + cc])       = v01;
            *reinterpret_cast<float2*>(&Cb[(size_t)(r0 + 8) * NSEQ + cc]) = v23;
        }
    }
}

extern "C" void kernel_launch(void* const* d_in, const int* in_sizes, int n_in,
                              void* d_out, int out_size) {
    const float* P  = (const float*)d_in[0];   // [8, 2048, 384]
    const float* W  = (const float*)d_in[1];   // [384, 384]
    const float* bp = (const float*)d_in[2];   // [1]
    float* out = (float*)d_out;                // [8, 2048, 2048]
    (void)in_sizes; (void)n_in; (void)out_size;

    static bool attr_set = false;
    if (!attr_set) {
        cudaFuncSetAttribute(gemm_pw_f16,
                             cudaFuncAttributeMaxDynamicSharedMemorySize, SMEM_BYTES);
        cudaFuncSetAttribute(gemm_logits_k2,
                             cudaFuncAttributeMaxDynamicSharedMemorySize, SMEM_BYTES);
        attr_set = true;
    }

    // Prep: P -> fp16, W -> W^T fp16
    int n4 = BATCH * NSEQ * DDIM / 4;
    cvt_half_kernel<<<2048, 256>>>(reinterpret_cast<const float4*>(P), n4);
    wtrans_kernel<<<(DDIM * DDIM + 255) / 256, 256>>>(W);

    // Kernel 1: PW = P @ W (fp16 NT)
    dim3 g1(DDIM / BN2, (BATCH * NSEQ) / BM2, 1);    // (3, 64)
    gemm_pw_f16<<<g1, 256, SMEM_BYTES>>>(0);

    // Kernel 2: per-batch logits = PW @ P^T + b
    dim3 g2(NSEQ / BN2, NSEQ / BM2, BATCH);          // (16, 8, 8)
    gemm_logits_k2<<<g2, 256, SMEM_BYTES>>>(bp, out);
}